// round 1
// baseline (speedup 1.0000x reference)
#include <cuda_runtime.h>

// out[i] = |spherical[0]| * x[i]   — pure HBM streaming, float4 vectorized.
// x: 1,000,000 x 128 fp32 -> 128e6 elements, divisible by 4 -> 32e6 float4.

__global__ void __launch_bounds__(256) spherical_scale_kernel(
    const float4* __restrict__ x,
    const float* __restrict__ s,
    float4* __restrict__ out,
    long long n4)
{
    long long i = (long long)blockIdx.x * blockDim.x + threadIdx.x;
    float a = fabsf(__ldg(s));
    // grid-stride for safety (grid is sized to cover exactly, so one trip)
    long long stride = (long long)gridDim.x * blockDim.x;
    for (; i < n4; i += stride) {
        float4 v = x[i];
        v.x *= a; v.y *= a; v.z *= a; v.w *= a;
        out[i] = v;
    }
}

extern "C" void kernel_launch(void* const* d_in, const int* in_sizes, int n_in,
                              void* d_out, int out_size)
{
    const float* x = (const float*)d_in[0];       // 1e6 x 128 fp32
    const float* s = (const float*)d_in[1];       // 1 fp32
    float* out = (float*)d_out;

    long long n = (long long)in_sizes[0];         // 128,000,000
    long long n4 = n >> 2;                         // divisible by 4

    const int threads = 256;
    long long blocks = (n4 + threads - 1) / threads;
    if (blocks > 0x7FFFFFFFLL) blocks = 0x7FFFFFFFLL;

    spherical_scale_kernel<<<(unsigned)blocks, threads>>>(
        (const float4*)x, s, (float4*)out, n4);
}